// round 14
// baseline (speedup 1.0000x reference)
#include <cuda_runtime.h>
#include <cuda_fp16.h>
#include <cstdint>

#define NN 8192
#define DD 128
#define NC 10
#define BT 128
#define NB (NN / BT)
#define NOFF (NB * (NB - 1) / 2)     // 2016 off-diag tiles
#define NTILES (NOFF + NB)            // + 64 diag
#define PITCH 136
#define DP2 68

typedef unsigned long long ull;

__device__ float   g_x2[NN];
__device__ float   g_S[NN][NC];
__device__ ull     g_mpk[NN];
__device__ int     g_order[NN];
__device__ int     g_scls[NN];
__device__ float   g_sx2[NN];
__device__ int     g_cstart[NC];
__device__ int     g_count[NC];
__device__ __half2 g_Eh[NN][64];

__device__ __forceinline__ uint32_t smem_u32(const void* p) {
    uint32_t a;
    asm("{ .reg .u64 t; cvta.to.shared.u64 t, %1; cvt.u32.u64 %0, t; }" : "=r"(a) : "l"(p));
    return a;
}

#define LDSM4(r0, r1, r2, r3, addr)                                          \
    asm volatile("ldmatrix.sync.aligned.m8n8.x4.shared.b16 {%0,%1,%2,%3},[%4];" \
        : "=r"(r0), "=r"(r1), "=r"(r2), "=r"(r3) : "r"(addr))

#define MMA16816(cp, a0, a1, a2, a3, b0, b1)                                 \
    asm volatile("mma.sync.aligned.m16n8k16.row.col.f32.f16.f16.f32 "        \
        "{%0,%1,%2,%3},{%4,%5,%6,%7},{%8,%9},{%0,%1,%2,%3};"                 \
        : "+f"((cp)[0]), "+f"((cp)[1]), "+f"((cp)[2]), "+f"((cp)[3])         \
        : "r"(a0), "r"(a1), "r"(a2), "r"(a3), "r"(b0), "r"(b1))

#define ADD2(acc, v) \
    asm("add.rn.f32x2 %0, %0, %1;" : "+l"(acc) : "l"(v))
#define PACKF2(dst, lo, hi) \
    asm("mov.b64 %0, {%1, %2};" : "=l"(dst) : "f"(lo), "f"(hi))
#define UNPACKF2(lo, hi, src) \
    asm("mov.b64 {%0, %1}, %2;" : "=f"(lo), "=f"(hi) : "l"(src))

// ---------------------------------------------------------------------------
// Kernel 1: parallel stable (class,index) sort. 1 block, 1024 threads.
// ---------------------------------------------------------------------------
__global__ __launch_bounds__(1024)
void bh_table(const int* __restrict__ labels)
{
    __shared__ int wpre[32][NC];
    __shared__ int lofs[1024][NC];
    __shared__ int cst[NC];

    const int tid  = threadIdx.x;
    const int w    = tid >> 5;
    const int lane = tid & 31;
    const int base = tid * 8;

    int4 l0 = *reinterpret_cast<const int4*>(labels + base);
    int4 l1 = *reinterpret_cast<const int4*>(labels + base + 4);
    int lab[8] = {l0.x, l0.y, l0.z, l0.w, l1.x, l1.y, l1.z, l1.w};

    int lc[NC];
#pragma unroll
    for (int c = 0; c < NC; c++) lc[c] = 0;
#pragma unroll
    for (int i = 0; i < 8; i++)
#pragma unroll
        for (int c = 0; c < NC; c++) lc[c] += (lab[i] == c);

#pragma unroll
    for (int c = 0; c < NC; c++) {
        int v = lc[c], inc = v;
#pragma unroll
        for (int off = 1; off < 32; off <<= 1) {
            int o = __shfl_up_sync(0xffffffffu, inc, off);
            if (lane >= off) inc += o;
        }
        lofs[tid][c] = inc - v;
        if (lane == 31) wpre[w][c] = inc;
    }
    __syncthreads();

    if (tid < NC) {
        int run = 0;
        for (int t = 0; t < 32; t++) { int tmp = wpre[t][tid]; wpre[t][tid] = run; run += tmp; }
        g_count[tid] = run;
    }
    __syncthreads();
    if (tid == 0) {
        int run = 0;
        for (int c = 0; c < NC; c++) { cst[c] = run; g_cstart[c] = run; run += g_count[c]; }
    }
    __syncthreads();

#pragma unroll
    for (int i = 0; i < 8; i++) {
        int c = lab[i];
        int rk = 0;
#pragma unroll
        for (int j = 0; j < 8; j++) rk += (j < i) && (lab[j] == c);
        int pos = cst[c] + wpre[w][c] + lofs[tid][c] + rk;
        g_order[pos] = base + i;
        g_scls[pos]  = c;
    }
}

// ---------------------------------------------------------------------------
// Kernel 2: pack sorted rows to fp16, compute norms, zero stats + out.
// ---------------------------------------------------------------------------
__global__ void bh_pack(const float* __restrict__ E, float* __restrict__ out)
{
    const int p    = (blockIdx.x * blockDim.x + threadIdx.x) >> 5;
    const int lane = threadIdx.x & 31;
    if (blockIdx.x == 0 && threadIdx.x == 0) out[0] = 0.0f;

    const int gi = g_order[p];
    float4 v = *reinterpret_cast<const float4*>(E + (size_t)gi * DD + lane * 4);
    g_Eh[p][lane * 2]     = __floats2half2_rn(v.x, v.y);
    g_Eh[p][lane * 2 + 1] = __floats2half2_rn(v.z, v.w);

    float s = v.x * v.x + v.y * v.y + v.z * v.z + v.w * v.w;
#pragma unroll
    for (int off = 16; off >= 1; off >>= 1)
        s += __shfl_xor_sync(0xffffffffu, s, off);
    if (lane == 0) { g_x2[gi] = s; g_sx2[p] = s; g_mpk[p] = 0ull; }
    if (lane < NC) g_S[p][lane] = 0.f;
}

// ---------------------------------------------------------------------------
// SHARE epilogue (class sets intersect; includes all diag tiles):
// clamped d, max tracking. Unchanged from R13.
// ---------------------------------------------------------------------------
__device__ __forceinline__ void epi_share(
    float (&cfr)[2][8][4],
    int wr, int wc, int g, int t, int tid, bool diag,
    int rowbase, int jbase, int srow, int scol,
    int cAr, int cBr, int cAc, int cBc,
    const float* sxr, const float* sxj,
    __half2* dsh, float* qA, float* qB, float* qV, int* qR)
{
    int   rowt[2][2], rcv[2][2];
    float xrv[2][2], sA[2][2], sBv[2][2], mv[2][2];
    int   mc[2][2];
#pragma unroll
    for (int mi = 0; mi < 2; ++mi)
#pragma unroll
        for (int h = 0; h < 2; ++h) {
            rowt[mi][h] = wr * 32 + mi * 16 + g + h * 8;
            xrv[mi][h]  = sxr[rowt[mi][h]];
            rcv[mi][h]  = (rowt[mi][h] < srow) ? cAr : cBr;
            sA[mi][h] = 0.f; sBv[mi][h] = 0.f; mv[mi][h] = -1.f; mc[mi][h] = 0;
        }

#pragma unroll
    for (int n = 0; n < 8; ++n) {
        const int  c0  = wc * 64 + n * 8 + t * 2;
        const float xj0 = sxj[c0], xj1 = sxj[c0 + 1];
        const bool a0 = c0 < scol, a1 = (c0 + 1) < scol;
        const int  cc0 = a0 ? cAc : cBc, cc1 = a1 ? cAc : cBc;
#pragma unroll
        for (int mi = 0; mi < 2; ++mi)
#pragma unroll
            for (int h = 0; h < 2; ++h) {
                float d0 = fmaxf(fmaf(-2.0f, cfr[mi][n][h * 2],     xrv[mi][h] + xj0), 0.0f);
                float d1 = fmaxf(fmaf(-2.0f, cfr[mi][n][h * 2 + 1], xrv[mi][h] + xj1), 0.0f);
                if (a0) sA[mi][h] += d0; else sBv[mi][h] += d0;
                if (a1) sA[mi][h] += d1; else sBv[mi][h] += d1;
                if (cc0 == rcv[mi][h] && d0 > mv[mi][h]) { mv[mi][h] = d0; mc[mi][h] = c0; }
                if (cc1 == rcv[mi][h] && d1 > mv[mi][h]) { mv[mi][h] = d1; mc[mi][h] = c0 + 1; }
                if (!diag)
                    dsh[rowt[mi][h] * DP2 + (c0 >> 1)] = __floats2half2_rn(d0, d1);
            }
    }

#pragma unroll
    for (int off = 2; off >= 1; off >>= 1) {
#pragma unroll
        for (int mi = 0; mi < 2; ++mi)
#pragma unroll
            for (int h = 0; h < 2; ++h) {
                sA[mi][h]  += __shfl_down_sync(0xffffffffu, sA[mi][h],  off, 4);
                sBv[mi][h] += __shfl_down_sync(0xffffffffu, sBv[mi][h], off, 4);
                float ov = __shfl_down_sync(0xffffffffu, mv[mi][h], off, 4);
                int   oc = __shfl_down_sync(0xffffffffu, mc[mi][h], off, 4);
                if (ov > mv[mi][h]) { mv[mi][h] = ov; mc[mi][h] = oc; }
            }
    }
    if (t == 0) {
#pragma unroll
        for (int mi = 0; mi < 2; ++mi)
#pragma unroll
            for (int h = 0; h < 2; ++h) {
                const int rp = rowbase + rowt[mi][h];
                atomicAdd(&g_S[rp][cAc], sA[mi][h]);
                if (scol < BT) atomicAdd(&g_S[rp][cBc], sBv[mi][h]);
                if (mv[mi][h] >= 0.f)
                    atomicMax(&g_mpk[rp], (((ull)__float_as_uint(mv[mi][h])) << 32)
                                          | (unsigned)(jbase + mc[mi][h]));
            }
    }

    if (!diag) {
        __syncthreads();
        const int cp = tid & 63, q = tid >> 6;
        const int c0 = cp * 2, c1 = c0 + 1;
        const int cc0 = (c0 < scol) ? cAc : cBc;
        const int cc1 = (c1 < scol) ? cAc : cBc;
        float s0A = 0.f, s0B = 0.f, s1A = 0.f, s1B = 0.f;
        float m0 = -1.f, m1 = -1.f;
        int   r0 = 0, r1 = 0;
#pragma unroll 8
        for (int rr = 0; rr < 32; ++rr) {
            const int row = q * 32 + rr;
            float2 d = __half22float2(dsh[row * DP2 + cp]);
            const bool isA = row < srow;
            if (isA) { s0A += d.x; s1A += d.y; } else { s0B += d.x; s1B += d.y; }
            const int rc = isA ? cAr : cBr;
            if (rc == cc0 && d.x > m0) { m0 = d.x; r0 = row; }
            if (rc == cc1 && d.y > m1) { m1 = d.y; r1 = row; }
        }
        qA[q * 128 + c0] = s0A;  qA[q * 128 + c1] = s1A;
        qB[q * 128 + c0] = s0B;  qB[q * 128 + c1] = s1B;
        qV[q * 128 + c0] = m0;   qV[q * 128 + c1] = m1;
        qR[q * 128 + c0] = r0;   qR[q * 128 + c1] = r1;
        __syncthreads();

        if (tid < BT) {
            const int col = tid;
            float sAc = 0.f, sBc = 0.f, mvc = -1.f;
            int   mrc = 0;
#pragma unroll
            for (int qq = 0; qq < 4; ++qq) {
                sAc += qA[qq * 128 + col];
                sBc += qB[qq * 128 + col];
                float v = qV[qq * 128 + col];
                if (v > mvc) { mvc = v; mrc = qR[qq * 128 + col]; }
            }
            const int cpo = jbase + col;
            atomicAdd(&g_S[cpo][cAr], sAc);
            if (srow < BT) atomicAdd(&g_S[cpo][cBr], sBc);
            if (mvc >= 0.f)
                atomicMax(&g_mpk[cpo], (((ull)__float_as_uint(mvc)) << 32)
                                       | (unsigned)(rowbase + mrc));
        }
    }
}

// ---------------------------------------------------------------------------
// FAST epilogue (disjoint class sets; never diagonal): no clamp needed,
// class sums are affine in dot sums. Packed f32x2 accumulation of raw dots,
// raw-dot fp16 dump, affine-corrected publishes.
// ---------------------------------------------------------------------------
__device__ __forceinline__ void epi_fast(
    float (&cfr)[2][8][4],
    int wr, int wc, int g, int t, int tid,
    int rowbase, int jbase, int srow, int scol,
    int cAr, int cBr, int cAc, int cBc,
    const float* sxr, const float* sxj,
    float sumXjA, float sumXjB, float sumXrA, float sumXrB,
    __half2* dsh, float* qA, float* qB)
{
    int rowt[2][2];
    ull accA[2][2], accB[2][2];
    float fix[2][2];
#pragma unroll
    for (int mi = 0; mi < 2; ++mi)
#pragma unroll
        for (int h = 0; h < 2; ++h) {
            rowt[mi][h] = wr * 32 + mi * 16 + g + h * 8;
            accA[mi][h] = 0ull; accB[mi][h] = 0ull; fix[mi][h] = 0.f;
        }

#pragma unroll
    for (int n = 0; n < 8; ++n) {
        const int  c0 = wc * 64 + n * 8 + t * 2;
        const bool a0 = c0 < scol;      // pair class by its first column
#pragma unroll
        for (int mi = 0; mi < 2; ++mi)
#pragma unroll
            for (int h = 0; h < 2; ++h) {
                float lo = cfr[mi][n][h * 2], hi = cfr[mi][n][h * 2 + 1];
                ull pr; PACKF2(pr, lo, hi);
                if (a0) ADD2(accA[mi][h], pr); else ADD2(accB[mi][h], pr);
                dsh[rowt[mi][h] * DP2 + (c0 >> 1)] = __floats2half2_rn(lo, hi);
            }
    }
    // odd class boundary: column scol-1's pair partner (col==scol) was
    // misattributed to class A; move it.
    if (scol & 1) {
        const int cs = scol - 1;
        if ((cs >> 6) == wc && (((cs >> 1) & 3) == t)) {
            const int nf = (cs & 63) >> 3;
#pragma unroll
            for (int mi = 0; mi < 2; ++mi)
#pragma unroll
                for (int h = 0; h < 2; ++h)
                    fix[mi][h] = cfr[mi][nf][h * 2 + 1];
        }
    }

    float rA[2][2], rB[2][2];
#pragma unroll
    for (int mi = 0; mi < 2; ++mi)
#pragma unroll
        for (int h = 0; h < 2; ++h) {
            float lo, hi;
            UNPACKF2(lo, hi, accA[mi][h]);
            rA[mi][h] = lo + hi - fix[mi][h];
            UNPACKF2(lo, hi, accB[mi][h]);
            rB[mi][h] = lo + hi + fix[mi][h];
        }
#pragma unroll
    for (int off = 2; off >= 1; off >>= 1)
#pragma unroll
        for (int mi = 0; mi < 2; ++mi)
#pragma unroll
            for (int h = 0; h < 2; ++h) {
                rA[mi][h] += __shfl_down_sync(0xffffffffu, rA[mi][h], off, 4);
                rB[mi][h] += __shfl_down_sync(0xffffffffu, rB[mi][h], off, 4);
            }
    if (t == 0) {
#pragma unroll
        for (int mi = 0; mi < 2; ++mi)
#pragma unroll
            for (int h = 0; h < 2; ++h) {
                const int rp = rowbase + rowt[mi][h];
                const float xr = sxr[rowt[mi][h]];
                float addA = -2.f * rA[mi][h];
                if (wc == 0) addA += (float)scol * xr + sumXjA;   // constants once
                atomicAdd(&g_S[rp][cAc], addA);
                if (scol < BT) {
                    float addB = -2.f * rB[mi][h];
                    if (wc == 0) addB += (float)(BT - scol) * xr + sumXjB;
                    atomicAdd(&g_S[rp][cBc], addB);
                }
            }
    }
    __syncthreads();

    // col pass: packed dot sums by row class
    const int cp = tid & 63, q = tid >> 6;
    ull sA2 = 0ull, sB2 = 0ull;
#pragma unroll 8
    for (int rr = 0; rr < 32; ++rr) {
        const int row = q * 32 + rr;
        float2 d = __half22float2(dsh[row * DP2 + cp]);
        ull pr; PACKF2(pr, d.x, d.y);
        if (row < srow) ADD2(sA2, pr); else ADD2(sB2, pr);
    }
    {
        float loA, hiA, loB, hiB;
        UNPACKF2(loA, hiA, sA2);
        UNPACKF2(loB, hiB, sB2);
        qA[q * 128 + cp * 2]     = loA;
        qA[q * 128 + cp * 2 + 1] = hiA;
        qB[q * 128 + cp * 2]     = loB;
        qB[q * 128 + cp * 2 + 1] = hiB;
    }
    __syncthreads();

    if (tid < BT) {
        const int col = tid;
        float sAc = 0.f, sBc = 0.f;
#pragma unroll
        for (int qq = 0; qq < 4; ++qq) {
            sAc += qA[qq * 128 + col];
            sBc += qB[qq * 128 + col];
        }
        const float xc = sxj[col];
        const int cpo = jbase + col;
        atomicAdd(&g_S[cpo][cAr], -2.f * sAc + (float)srow * xc + sumXrA);
        if (srow < BT)
            atomicAdd(&g_S[cpo][cBr], -2.f * sBc + (float)(BT - srow) * xc + sumXrB);
    }
}

// ---------------------------------------------------------------------------
// Kernel 3: symmetric-tile Gram via HMMA; off-diag tiles first; epilogue
// specialized: affine fast path when row/col class sets are disjoint.
// ---------------------------------------------------------------------------
__global__ __launch_bounds__(256, 2)
void bh_main()
{
    extern __shared__ char smraw[];
    const uint32_t sb = smem_u32(smraw);
    __half*  Ah  = (__half*)smraw;
    __half2* dsh = (__half2*)smraw;
    float*   qA  = (float*)(smraw + 128 * DP2 * 4);
    float*   qB  = qA + 512;
    float*   qV  = qB + 512;
    int*     qR  = (int*)(qV + 512);
    float*   sxj = (float*)(smraw + 69632);
    float*   sxr = sxj + 128;
    __shared__ int sb_col, sb_row;
    __shared__ float sXsum[4];   // [ΣxjA, ΣxjB, ΣxrA, ΣxrB]

    const int tid  = threadIdx.x;
    const int w    = tid >> 5;
    const int lane = tid & 31;
    const int g    = lane >> 2, t = lane & 3;
    const int wr   = w & 3, wc = w >> 2;

    int bi, bj;
    const int id = (int)blockIdx.x;
    if (id < NOFF) {
        float bf = (float)id;
        bi = (int)(62.5f - sqrtf(fmaxf(62.5f * 62.5f - 2.0f * bf, 0.0f)));
        if (bi < 0) bi = 0;
        while ((bi + 1) * (2 * NB - 2 - bi) / 2 <= id) ++bi;
        while (bi * (2 * NB - 1 - bi) / 2 > id) --bi;
        bj = bi + 1 + (id - bi * (2 * NB - 1 - bi) / 2);
    } else {
        bi = bj = id - NOFF;
    }
    const bool diag = (bi == bj);
    const int rowbase = bi * BT;
    const int jbase   = bj * BT;

    if (tid == 0) { sb_col = BT; sb_row = BT; }
    if (tid < 4) sXsum[tid] = 0.f;
    __syncthreads();
    if (tid < BT - 1) {
        if (g_scls[jbase + tid + 1]   != g_scls[jbase + tid])   atomicMin(&sb_col, tid + 1);
        if (g_scls[rowbase + tid + 1] != g_scls[rowbase + tid]) atomicMin(&sb_row, tid + 1);
    }

    // ---- tile loads ----
#pragma unroll
    for (int it = 0; it < 8; ++it) {
        int idx = tid + it * 256;
        int row = idx >> 4, c = idx & 15;
        uint4 v = *reinterpret_cast<const uint4*>(
            reinterpret_cast<const char*>(&g_Eh[rowbase + row][0]) + c * 16);
        *reinterpret_cast<uint4*>(Ah + row * PITCH + c * 8) = v;
    }
    if (!diag) {
        __half* Bh = Ah + 128 * PITCH;
#pragma unroll
        for (int it = 0; it < 8; ++it) {
            int idx = tid + it * 256;
            int row = idx >> 4, c = idx & 15;
            uint4 v = *reinterpret_cast<const uint4*>(
                reinterpret_cast<const char*>(&g_Eh[jbase + row][0]) + c * 16);
            *reinterpret_cast<uint4*>(Bh + row * PITCH + c * 8) = v;
        }
    }
    if (tid < BT) { sxj[tid] = g_sx2[jbase + tid]; sxr[tid] = g_sx2[rowbase + tid]; }
    __syncthreads();

    // per-tile class-segment norm sums (for the affine fast path)
    if (tid < BT) {
        atomicAdd(&sXsum[(tid < sb_col) ? 0 : 1], sxj[tid]);
    } else {
        const int r = tid - BT;
        atomicAdd(&sXsum[(r < sb_row) ? 2 : 3], sxr[r]);
    }

    // ---- MMA mainloop ----
    const uint32_t aBase0 = sb + ((wr * 32 + (lane & 15)) * PITCH + ((lane >> 4) << 3)) * 2;
    const uint32_t aBase1 = aBase0 + 16 * PITCH * 2;
    const uint32_t bTile  = diag ? sb : (sb + 128 * PITCH * 2);
    const uint32_t bBase  = bTile + ((wc * 64 + (lane & 7) + ((lane >> 4) << 3)) * PITCH
                                     + (((lane >> 3) & 1) << 3)) * 2;

    float cfr[2][8][4];
#pragma unroll
    for (int mi = 0; mi < 2; ++mi)
#pragma unroll
        for (int n = 0; n < 8; ++n)
#pragma unroll
            for (int q = 0; q < 4; ++q) cfr[mi][n][q] = 0.f;

#pragma unroll
    for (int ks = 0; ks < 8; ++ks) {
        uint32_t a00, a01, a02, a03, a10, a11, a12, a13;
        LDSM4(a00, a01, a02, a03, aBase0 + ks * 32);
        LDSM4(a10, a11, a12, a13, aBase1 + ks * 32);
#pragma unroll
        for (int np = 0; np < 4; ++np) {
            uint32_t b0, b1, b2, b3;
            LDSM4(b0, b1, b2, b3, bBase + np * (16 * PITCH * 2) + ks * 32);
            MMA16816(cfr[0][np * 2],     a00, a01, a02, a03, b0, b1);
            MMA16816(cfr[0][np * 2 + 1], a00, a01, a02, a03, b2, b3);
            MMA16816(cfr[1][np * 2],     a10, a11, a12, a13, b0, b1);
            MMA16816(cfr[1][np * 2 + 1], a10, a11, a12, a13, b2, b3);
        }
    }
    __syncthreads();

    const int scol = sb_col, srow = sb_row;
    const int cAc = g_scls[jbase],   cBc = g_scls[jbase + BT - 1];
    const int cAr = g_scls[rowbase], cBr = g_scls[rowbase + BT - 1];
    const bool share = (cAc <= cBr) && (cAr <= cBc);

    if (share)
        epi_share(cfr, wr, wc, g, t, tid, diag, rowbase, jbase,
                  srow, scol, cAr, cBr, cAc, cBc, sxr, sxj,
                  dsh, qA, qB, qV, qR);
    else
        epi_fast(cfr, wr, wc, g, t, tid, rowbase, jbase,
                 srow, scol, cAr, cBr, cAc, cBc, sxr, sxj,
                 sXsum[0], sXsum[1], sXsum[2], sXsum[3],
                 dsh, qA, qB);
}

// ---------------------------------------------------------------------------
// Kernel 4: finalize — warp per sorted anchor: argmin, class walk,
// EXACT fp32 recompute of d_pos (tracked argmax) and d_neg.
// ---------------------------------------------------------------------------
__global__ void bh_final(const float* __restrict__ E, float* __restrict__ out)
{
    const int p    = (blockIdx.x * blockDim.x + threadIdx.x) >> 5;
    const int lane = threadIdx.x & 31;

    float T = 0.f, S[NC];
#pragma unroll
    for (int c = 0; c < NC; c++) { S[c] = g_S[p][c]; T += S[c]; }

    float best = 3.4e38f;
    int   ks   = 0;
#pragma unroll
    for (int c = 0; c < NC; c++) {
        float nd = T - S[c];
        if (nd < best) { best = nd; ks = c; }
    }

    const int la = g_scls[p];
    int rem = ks, js = 0;
#pragma unroll
    for (int c = 0; c < NC; c++) {
        if (c == la) continue;
        int cn = g_count[c];
        if (rem < cn) { js = g_order[g_cstart[c] + rem]; rem = 0x7fffffff; }
        else rem -= cn;
    }

    const ull key = g_mpk[p];
    const int jpq = (int)(key & 0xffffffffu);
    const int gjp = g_order[jpq];
    const int gi  = g_order[p];

    float4 a  = *reinterpret_cast<const float4*>(E + (size_t)gi  * DD + lane * 4);
    float4 bp = *reinterpret_cast<const float4*>(E + (size_t)gjp * DD + lane * 4);
    float4 bn = *reinterpret_cast<const float4*>(E + (size_t)js  * DD + lane * 4);
    float dotp = a.x * bp.x + a.y * bp.y + a.z * bp.z + a.w * bp.w;
    float dotn = a.x * bn.x + a.y * bn.y + a.z * bn.z + a.w * bn.w;
#pragma unroll
    for (int off = 16; off >= 1; off >>= 1) {
        dotp += __shfl_xor_sync(0xffffffffu, dotp, off);
        dotn += __shfl_xor_sync(0xffffffffu, dotn, off);
    }

    float loss = 0.f;
    if (lane == 0) {
        float dp = fmaxf(g_x2[gi] + g_x2[gjp] - 2.0f * dotp, 0.0f);
        float dn = fmaxf(g_x2[gi] + g_x2[js]  - 2.0f * dotn, 0.0f);
        loss = fmaxf(dp - dn + 1.0f, 0.0f);
    }

    __shared__ float wsum[8];
    if (lane == 0) wsum[threadIdx.x >> 5] = loss;
    __syncthreads();
    if (threadIdx.x == 0) {
        float s = 0.f;
#pragma unroll
        for (int w = 0; w < 8; w++) s += wsum[w];
        atomicAdd(out, s * (1.0f / NN));
    }
}

// ---------------------------------------------------------------------------
extern "C" void kernel_launch(void* const* d_in, const int* in_sizes, int n_in,
                              void* d_out, int out_size)
{
    const float* E      = (const float*)d_in[0];
    const int*   labels = (const int*)d_in[1];
    float*       out    = (float*)d_out;

    const int smem = 69632 + 2 * 128 * 4;
    cudaFuncSetAttribute(bh_main, cudaFuncAttributeMaxDynamicSharedMemorySize, smem);

    bh_table<<<1, 1024>>>(labels);
    bh_pack<<<NN * 32 / 256, 256>>>(E, out);
    bh_main<<<NTILES, 256, smem>>>();
    bh_final<<<NN * 32 / 256, 256>>>(E, out);
}

// round 15
// speedup vs baseline: 1.6475x; 1.6475x over previous
#include <cuda_runtime.h>
#include <cuda_fp16.h>
#include <cstdint>

#define NN 8192
#define DD 128
#define NC 10
#define BT 128
#define NB (NN / BT)
#define NOFF (NB * (NB - 1) / 2)     // 2016 off-diag tiles
#define NTILES (NOFF + NB)            // + 64 diag
#define PITCH 136
#define DP2 68

typedef unsigned long long ull;

__device__ float   g_x2[NN];
__device__ float   g_S[NN][NC];
__device__ ull     g_mpk[NN];
__device__ int     g_order[NN];
__device__ int     g_scls[NN];
__device__ float   g_sx2[NN];
__device__ int     g_cstart[NC];
__device__ int     g_count[NC];
__device__ __half2 g_Eh[NN][64];

__device__ __forceinline__ uint32_t smem_u32(const void* p) {
    uint32_t a;
    asm("{ .reg .u64 t; cvta.to.shared.u64 t, %1; cvt.u32.u64 %0, t; }" : "=r"(a) : "l"(p));
    return a;
}

#define LDSM4(r0, r1, r2, r3, addr)                                          \
    asm volatile("ldmatrix.sync.aligned.m8n8.x4.shared.b16 {%0,%1,%2,%3},[%4];" \
        : "=r"(r0), "=r"(r1), "=r"(r2), "=r"(r3) : "r"(addr))

#define MMA16816(cp, a0, a1, a2, a3, b0, b1)                                 \
    asm volatile("mma.sync.aligned.m16n8k16.row.col.f32.f16.f16.f32 "        \
        "{%0,%1,%2,%3},{%4,%5,%6,%7},{%8,%9},{%0,%1,%2,%3};"                 \
        : "+f"((cp)[0]), "+f"((cp)[1]), "+f"((cp)[2]), "+f"((cp)[3])         \
        : "r"(a0), "r"(a1), "r"(a2), "r"(a3), "r"(b0), "r"(b1))

// ---------------------------------------------------------------------------
// Kernel 1: parallel stable (class,index) sort. 1 block, 1024 threads.
// ---------------------------------------------------------------------------
__global__ __launch_bounds__(1024)
void bh_table(const int* __restrict__ labels)
{
    __shared__ int wpre[32][NC];
    __shared__ int lofs[1024][NC];
    __shared__ int cst[NC];

    const int tid  = threadIdx.x;
    const int w    = tid >> 5;
    const int lane = tid & 31;
    const int base = tid * 8;

    int4 l0 = *reinterpret_cast<const int4*>(labels + base);
    int4 l1 = *reinterpret_cast<const int4*>(labels + base + 4);
    int lab[8] = {l0.x, l0.y, l0.z, l0.w, l1.x, l1.y, l1.z, l1.w};

    int lc[NC];
#pragma unroll
    for (int c = 0; c < NC; c++) lc[c] = 0;
#pragma unroll
    for (int i = 0; i < 8; i++)
#pragma unroll
        for (int c = 0; c < NC; c++) lc[c] += (lab[i] == c);

#pragma unroll
    for (int c = 0; c < NC; c++) {
        int v = lc[c], inc = v;
#pragma unroll
        for (int off = 1; off < 32; off <<= 1) {
            int o = __shfl_up_sync(0xffffffffu, inc, off);
            if (lane >= off) inc += o;
        }
        lofs[tid][c] = inc - v;
        if (lane == 31) wpre[w][c] = inc;
    }
    __syncthreads();

    if (tid < NC) {
        int run = 0;
        for (int t = 0; t < 32; t++) { int tmp = wpre[t][tid]; wpre[t][tid] = run; run += tmp; }
        g_count[tid] = run;
    }
    __syncthreads();
    if (tid == 0) {
        int run = 0;
        for (int c = 0; c < NC; c++) { cst[c] = run; g_cstart[c] = run; run += g_count[c]; }
    }
    __syncthreads();

#pragma unroll
    for (int i = 0; i < 8; i++) {
        int c = lab[i];
        int rk = 0;
#pragma unroll
        for (int j = 0; j < 8; j++) rk += (j < i) && (lab[j] == c);
        int pos = cst[c] + wpre[w][c] + lofs[tid][c] + rk;
        g_order[pos] = base + i;
        g_scls[pos]  = c;
    }
}

// ---------------------------------------------------------------------------
// Kernel 2: pack sorted rows to fp16, compute norms, zero stats + out.
// ---------------------------------------------------------------------------
__global__ void bh_pack(const float* __restrict__ E, float* __restrict__ out)
{
    const int p    = (blockIdx.x * blockDim.x + threadIdx.x) >> 5;
    const int lane = threadIdx.x & 31;
    if (blockIdx.x == 0 && threadIdx.x == 0) out[0] = 0.0f;

    const int gi = g_order[p];
    float4 v = *reinterpret_cast<const float4*>(E + (size_t)gi * DD + lane * 4);
    g_Eh[p][lane * 2]     = __floats2half2_rn(v.x, v.y);
    g_Eh[p][lane * 2 + 1] = __floats2half2_rn(v.z, v.w);

    float s = v.x * v.x + v.y * v.y + v.z * v.z + v.w * v.w;
#pragma unroll
    for (int off = 16; off >= 1; off >>= 1)
        s += __shfl_xor_sync(0xffffffffu, s, off);
    if (lane == 0) { g_x2[gi] = s; g_sx2[p] = s; g_mpk[p] = 0ull; }
    if (lane < NC) g_S[p][lane] = 0.f;
}

// ---------------------------------------------------------------------------
// Templated epilogue: SHARE = row/col class sets intersect (max tracking on).
// ---------------------------------------------------------------------------
template <bool SHARE>
__device__ __forceinline__ void tile_epilogue(
    float (&cfr)[2][8][4],
    int wr, int wc, int g, int t, int tid, bool diag,
    int rowbase, int jbase, int srow, int scol,
    int cAr, int cBr, int cAc, int cBc,
    const float* sxr, const float* sxj,
    __half2* dsh, float* qA, float* qB, float* qV, int* qR)
{
    int   rowt[2][2], rcv[2][2];
    float xrv[2][2], sA[2][2], sBv[2][2], mv[2][2];
    int   mc[2][2];
#pragma unroll
    for (int mi = 0; mi < 2; ++mi)
#pragma unroll
        for (int h = 0; h < 2; ++h) {
            rowt[mi][h] = wr * 32 + mi * 16 + g + h * 8;
            xrv[mi][h]  = sxr[rowt[mi][h]];
            rcv[mi][h]  = (rowt[mi][h] < srow) ? cAr : cBr;
            sA[mi][h] = 0.f; sBv[mi][h] = 0.f; mv[mi][h] = -1.f; mc[mi][h] = 0;
        }

#pragma unroll
    for (int n = 0; n < 8; ++n) {
        const int  c0  = wc * 64 + n * 8 + t * 2;
        const float xj0 = sxj[c0], xj1 = sxj[c0 + 1];
        const bool a0 = c0 < scol, a1 = (c0 + 1) < scol;
        const int  cc0 = a0 ? cAc : cBc, cc1 = a1 ? cAc : cBc;
#pragma unroll
        for (int mi = 0; mi < 2; ++mi)
#pragma unroll
            for (int h = 0; h < 2; ++h) {
                float d0 = fmaxf(fmaf(-2.0f, cfr[mi][n][h * 2],     xrv[mi][h] + xj0), 0.0f);
                float d1 = fmaxf(fmaf(-2.0f, cfr[mi][n][h * 2 + 1], xrv[mi][h] + xj1), 0.0f);
                if (a0) sA[mi][h] += d0; else sBv[mi][h] += d0;
                if (a1) sA[mi][h] += d1; else sBv[mi][h] += d1;
                if (SHARE) {
                    if (cc0 == rcv[mi][h] && d0 > mv[mi][h]) { mv[mi][h] = d0; mc[mi][h] = c0; }
                    if (cc1 == rcv[mi][h] && d1 > mv[mi][h]) { mv[mi][h] = d1; mc[mi][h] = c0 + 1; }
                }
                if (!diag)
                    dsh[rowt[mi][h] * DP2 + (c0 >> 1)] = __floats2half2_rn(d0, d1);
            }
    }

#pragma unroll
    for (int off = 2; off >= 1; off >>= 1) {
#pragma unroll
        for (int mi = 0; mi < 2; ++mi)
#pragma unroll
            for (int h = 0; h < 2; ++h) {
                sA[mi][h]  += __shfl_down_sync(0xffffffffu, sA[mi][h],  off, 4);
                sBv[mi][h] += __shfl_down_sync(0xffffffffu, sBv[mi][h], off, 4);
                if (SHARE) {
                    float ov = __shfl_down_sync(0xffffffffu, mv[mi][h], off, 4);
                    int   oc = __shfl_down_sync(0xffffffffu, mc[mi][h], off, 4);
                    if (ov > mv[mi][h]) { mv[mi][h] = ov; mc[mi][h] = oc; }
                }
            }
    }
    if (t == 0) {
#pragma unroll
        for (int mi = 0; mi < 2; ++mi)
#pragma unroll
            for (int h = 0; h < 2; ++h) {
                const int rp = rowbase + rowt[mi][h];
                atomicAdd(&g_S[rp][cAc], sA[mi][h]);
                if (scol < BT) atomicAdd(&g_S[rp][cBc], sBv[mi][h]);
                if (SHARE && mv[mi][h] >= 0.f)
                    atomicMax(&g_mpk[rp], (((ull)__float_as_uint(mv[mi][h])) << 32)
                                          | (unsigned)(jbase + mc[mi][h]));
            }
    }

    // ---- col pass over fp16 d (off-diagonal only) ----
    if (!diag) {
        __syncthreads();
        const int cp = tid & 63, q = tid >> 6;
        const int c0 = cp * 2, c1 = c0 + 1;
        const int cc0 = (c0 < scol) ? cAc : cBc;
        const int cc1 = (c1 < scol) ? cAc : cBc;
        float s0A = 0.f, s0B = 0.f, s1A = 0.f, s1B = 0.f;
        float m0 = -1.f, m1 = -1.f;
        int   r0 = 0, r1 = 0;
#pragma unroll 8
        for (int rr = 0; rr < 32; ++rr) {
            const int row = q * 32 + rr;
            float2 d = __half22float2(dsh[row * DP2 + cp]);
            const bool isA = row < srow;
            if (isA) { s0A += d.x; s1A += d.y; } else { s0B += d.x; s1B += d.y; }
            if (SHARE) {
                const int rc = isA ? cAr : cBr;
                if (rc == cc0 && d.x > m0) { m0 = d.x; r0 = row; }
                if (rc == cc1 && d.y > m1) { m1 = d.y; r1 = row; }
            }
        }
        qA[q * 128 + c0] = s0A;  qA[q * 128 + c1] = s1A;
        qB[q * 128 + c0] = s0B;  qB[q * 128 + c1] = s1B;
        if (SHARE) {
            qV[q * 128 + c0] = m0;   qV[q * 128 + c1] = m1;
            qR[q * 128 + c0] = r0;   qR[q * 128 + c1] = r1;
        }
        __syncthreads();

        if (tid < BT) {
            const int col = tid;
            float sAc = 0.f, sBc = 0.f, mvc = -1.f;
            int   mrc = 0;
#pragma unroll
            for (int qq = 0; qq < 4; ++qq) {
                sAc += qA[qq * 128 + col];
                sBc += qB[qq * 128 + col];
                if (SHARE) {
                    float v = qV[qq * 128 + col];
                    if (v > mvc) { mvc = v; mrc = qR[qq * 128 + col]; }
                }
            }
            const int cpo = jbase + col;
            atomicAdd(&g_S[cpo][cAr], sAc);
            if (srow < BT) atomicAdd(&g_S[cpo][cBr], sBc);
            if (SHARE && mvc >= 0.f)
                atomicMax(&g_mpk[cpo], (((ull)__float_as_uint(mvc)) << 32)
                                       | (unsigned)(rowbase + mrc));
        }
    }
}

// ---------------------------------------------------------------------------
// Kernel 3: symmetric-tile Gram via HMMA; off-diag tiles scheduled first,
// diag tiles in the tail; epilogue specialized on class-sharing.
// ---------------------------------------------------------------------------
__global__ __launch_bounds__(256, 2)
void bh_main()
{
    extern __shared__ char smraw[];
    const uint32_t sb = smem_u32(smraw);
    __half*  Ah  = (__half*)smraw;
    __half2* dsh = (__half2*)smraw;
    float*   qA  = (float*)(smraw + 128 * DP2 * 4);
    float*   qB  = qA + 512;
    float*   qV  = qB + 512;
    int*     qR  = (int*)(qV + 512);
    float*   sxj = (float*)(smraw + 69632);
    float*   sxr = sxj + 128;
    __shared__ int sb_col, sb_row;

    const int tid  = threadIdx.x;
    const int w    = tid >> 5;
    const int lane = tid & 31;
    const int g    = lane >> 2, t = lane & 3;
    const int wr   = w & 3, wc = w >> 2;

    // schedule decode: off-diag (bi<bj) first, then diag
    int bi, bj;
    const int id = (int)blockIdx.x;
    if (id < NOFF) {
        float bf = (float)id;
        bi = (int)(62.5f - sqrtf(fmaxf(62.5f * 62.5f - 2.0f * bf, 0.0f)));
        if (bi < 0) bi = 0;
        while ((bi + 1) * (2 * NB - 2 - bi) / 2 <= id) ++bi;
        while (bi * (2 * NB - 1 - bi) / 2 > id) --bi;
        bj = bi + 1 + (id - bi * (2 * NB - 1 - bi) / 2);
    } else {
        bi = bj = id - NOFF;
    }
    const bool diag = (bi == bj);
    const int rowbase = bi * BT;
    const int jbase   = bj * BT;

    if (tid == 0) { sb_col = BT; sb_row = BT; }
    __syncthreads();
    if (tid < BT - 1) {
        if (g_scls[jbase + tid + 1]   != g_scls[jbase + tid])   atomicMin(&sb_col, tid + 1);
        if (g_scls[rowbase + tid + 1] != g_scls[rowbase + tid]) atomicMin(&sb_row, tid + 1);
    }

    // ---- tile loads ----
#pragma unroll
    for (int it = 0; it < 8; ++it) {
        int idx = tid + it * 256;
        int row = idx >> 4, c = idx & 15;
        uint4 v = *reinterpret_cast<const uint4*>(
            reinterpret_cast<const char*>(&g_Eh[rowbase + row][0]) + c * 16);
        *reinterpret_cast<uint4*>(Ah + row * PITCH + c * 8) = v;
    }
    if (!diag) {
        __half* Bh = Ah + 128 * PITCH;
#pragma unroll
        for (int it = 0; it < 8; ++it) {
            int idx = tid + it * 256;
            int row = idx >> 4, c = idx & 15;
            uint4 v = *reinterpret_cast<const uint4*>(
                reinterpret_cast<const char*>(&g_Eh[jbase + row][0]) + c * 16);
            *reinterpret_cast<uint4*>(Bh + row * PITCH + c * 8) = v;
        }
    }
    if (tid < BT) { sxj[tid] = g_sx2[jbase + tid]; sxr[tid] = g_sx2[rowbase + tid]; }
    __syncthreads();

    // ---- MMA mainloop ----
    const uint32_t aBase0 = sb + ((wr * 32 + (lane & 15)) * PITCH + ((lane >> 4) << 3)) * 2;
    const uint32_t aBase1 = aBase0 + 16 * PITCH * 2;
    const uint32_t bTile  = diag ? sb : (sb + 128 * PITCH * 2);
    const uint32_t bBase  = bTile + ((wc * 64 + (lane & 7) + ((lane >> 4) << 3)) * PITCH
                                     + (((lane >> 3) & 1) << 3)) * 2;

    float cfr[2][8][4];
#pragma unroll
    for (int mi = 0; mi < 2; ++mi)
#pragma unroll
        for (int n = 0; n < 8; ++n)
#pragma unroll
            for (int q = 0; q < 4; ++q) cfr[mi][n][q] = 0.f;

#pragma unroll
    for (int ks = 0; ks < 8; ++ks) {
        uint32_t a00, a01, a02, a03, a10, a11, a12, a13;
        LDSM4(a00, a01, a02, a03, aBase0 + ks * 32);
        LDSM4(a10, a11, a12, a13, aBase1 + ks * 32);
#pragma unroll
        for (int np = 0; np < 4; ++np) {
            uint32_t b0, b1, b2, b3;
            LDSM4(b0, b1, b2, b3, bBase + np * (16 * PITCH * 2) + ks * 32);
            MMA16816(cfr[0][np * 2],     a00, a01, a02, a03, b0, b1);
            MMA16816(cfr[0][np * 2 + 1], a00, a01, a02, a03, b2, b3);
            MMA16816(cfr[1][np * 2],     a10, a11, a12, a13, b0, b1);
            MMA16816(cfr[1][np * 2 + 1], a10, a11, a12, a13, b2, b3);
        }
    }
    __syncthreads();

    const int scol = sb_col, srow = sb_row;
    const int cAc = g_scls[jbase],   cBc = g_scls[jbase + BT - 1];
    const int cAr = g_scls[rowbase], cBr = g_scls[rowbase + BT - 1];

    // class intervals intersect? (sorted order: cAr<=cBr, cAc<=cBc, bi<=bj)
    const bool share = (cAc <= cBr) && (cAr <= cBc);

    if (share)
        tile_epilogue<true >(cfr, wr, wc, g, t, tid, diag, rowbase, jbase,
                             srow, scol, cAr, cBr, cAc, cBc, sxr, sxj,
                             dsh, qA, qB, qV, qR);
    else
        tile_epilogue<false>(cfr, wr, wc, g, t, tid, diag, rowbase, jbase,
                             srow, scol, cAr, cBr, cAc, cBc, sxr, sxj,
                             dsh, qA, qB, qV, qR);
}

// ---------------------------------------------------------------------------
// Kernel 4: finalize — warp per sorted anchor: argmin, class walk,
// EXACT fp32 recompute of d_pos (tracked argmax) and d_neg.
// ---------------------------------------------------------------------------
__global__ void bh_final(const float* __restrict__ E, float* __restrict__ out)
{
    const int p    = (blockIdx.x * blockDim.x + threadIdx.x) >> 5;
    const int lane = threadIdx.x & 31;

    float T = 0.f, S[NC];
#pragma unroll
    for (int c = 0; c < NC; c++) { S[c] = g_S[p][c]; T += S[c]; }

    float best = 3.4e38f;
    int   ks   = 0;
#pragma unroll
    for (int c = 0; c < NC; c++) {
        float nd = T - S[c];
        if (nd < best) { best = nd; ks = c; }
    }

    const int la = g_scls[p];
    int rem = ks, js = 0;
#pragma unroll
    for (int c = 0; c < NC; c++) {
        if (c == la) continue;
        int cn = g_count[c];
        if (rem < cn) { js = g_order[g_cstart[c] + rem]; rem = 0x7fffffff; }
        else rem -= cn;
    }

    const ull key = g_mpk[p];
    const int jpq = (int)(key & 0xffffffffu);
    const int gjp = g_order[jpq];
    const int gi  = g_order[p];

    float4 a  = *reinterpret_cast<const float4*>(E + (size_t)gi  * DD + lane * 4);
    float4 bp = *reinterpret_cast<const float4*>(E + (size_t)gjp * DD + lane * 4);
    float4 bn = *reinterpret_cast<const float4*>(E + (size_t)js  * DD + lane * 4);
    float dotp = a.x * bp.x + a.y * bp.y + a.z * bp.z + a.w * bp.w;
    float dotn = a.x * bn.x + a.y * bn.y + a.z * bn.z + a.w * bn.w;
#pragma unroll
    for (int off = 16; off >= 1; off >>= 1) {
        dotp += __shfl_xor_sync(0xffffffffu, dotp, off);
        dotn += __shfl_xor_sync(0xffffffffu, dotn, off);
    }

    float loss = 0.f;
    if (lane == 0) {
        float dp = fmaxf(g_x2[gi] + g_x2[gjp] - 2.0f * dotp, 0.0f);
        float dn = fmaxf(g_x2[gi] + g_x2[js]  - 2.0f * dotn, 0.0f);
        loss = fmaxf(dp - dn + 1.0f, 0.0f);
    }

    __shared__ float wsum[8];
    if (lane == 0) wsum[threadIdx.x >> 5] = loss;
    __syncthreads();
    if (threadIdx.x == 0) {
        float s = 0.f;
#pragma unroll
        for (int w = 0; w < 8; w++) s += wsum[w];
        atomicAdd(out, s * (1.0f / NN));
    }
}

// ---------------------------------------------------------------------------
extern "C" void kernel_launch(void* const* d_in, const int* in_sizes, int n_in,
                              void* d_out, int out_size)
{
    const float* E      = (const float*)d_in[0];
    const int*   labels = (const int*)d_in[1];
    float*       out    = (float*)d_out;

    const int smem = 69632 + 2 * 128 * 4;
    cudaFuncSetAttribute(bh_main, cudaFuncAttributeMaxDynamicSharedMemorySize, smem);

    bh_table<<<1, 1024>>>(labels);
    bh_pack<<<NN * 32 / 256, 256>>>(E, out);
    bh_main<<<NTILES, 256, smem>>>();
    bh_final<<<NN * 32 / 256, 256>>>(E, out);
}